// round 4
// baseline (speedup 1.0000x reference)
#include <cuda_runtime.h>

#define SEQ   1024
#define BATCH 512
#define NC    48
#define FULL  0xffffffffu
#define PD    4          // global prefetch depth (steps)

static __device__ __forceinline__ float frcp(float x) {
    float r; asm("rcp.approx.f32 %0, %1;" : "=f"(r) : "f"(x)); return r;
}

// ---------------------------------------------------------------------------
// Fused kernel. Block = 256 threads, 4 batches per block:
//   warps 0-3: forward algorithm (logZ) for batch 4*blk+wid  (one per SMSP)
//   warps 4-7: target-path score X, handed over via shared flag.
//
// logZ: exp-domain recurrence u_t = diag(w_t) * E^T * u_{t-1},
// E = exp(transitions) in registers (scalar, one column pair per lane).
// alpha exchanged by shfl broadcast (R1 loop — measured fastest per step).
// Delayed renormalization: r = alpha_prev[0] = the i=0 broadcast (free);
// rcp/log run concurrently with the dot; Mlog += log(r) compensates exactly.
// ---------------------------------------------------------------------------
__global__ __launch_bounds__(256, 1) void crf_fused_kernel(
    const float* __restrict__ scores,
    const int*   __restrict__ target,
    const int*   __restrict__ lengths,
    const float* __restrict__ trans,
    float*       __restrict__ out)
{
    __shared__ float sh_X[4];
    __shared__ int   sh_flag[4];

    const int wid  = threadIdx.x >> 5;
    const int lane = threadIdx.x & 31;

    if (wid < 4 && lane == 0) sh_flag[wid] = 0;
    __syncthreads();

    if (wid >= 4) {
        // ---------------- X role (overlapped with logZ loop) ----------------
        const int w = wid - 4;
        const int b = blockIdx.x * 4 + w;
        const int L = lengths[b];
        float part = 0.0f;
        for (int t = lane; t < L; t += 32) {
            const int tgt = target[t * BATCH + b];
            float v = scores[((size_t)t * BATCH + b) * NC + tgt];
            if (t > 0) v += trans[target[(t - 1) * BATCH + b] * NC + tgt];
            part += v;
        }
#pragma unroll
        for (int o = 16; o > 0; o >>= 1)
            part += __shfl_xor_sync(FULL, part, o);
        if (lane == 0) {
            sh_X[w] = part;
            __threadfence_block();
            atomicExch(&sh_flag[w], 1);
        }
        return;
    }

    // ------------------------- logZ role -----------------------------------
    const int  b  = blockIdx.x * 4 + wid;
    const int  c0 = lane;                      // owned column 1 (always < 48)
    const bool v1 = (lane < 16);
    const int  c1 = v1 ? (lane + 32) : lane;   // owned column 2 (dup-safe)

    // exp(transitions): one column pair per lane, scalar registers.
    float eT0[NC], eT1[NC];
#pragma unroll
    for (int i = 0; i < NC; ++i) {
        eT0[i] = __expf(trans[i * NC + c0]);
        eT1[i] = v1 ? __expf(trans[i * NC + c1]) : 0.0f;
    }

    const int L = lengths[b];
    const float* sp0 = scores + (size_t)b * NC + c0;
    const float* sp1 = scores + (size_t)b * NC + c1;
    const size_t rowstride = (size_t)BATCH * NC;

    float a0   = __expf(sp0[0]);
    float a1   = v1 ? __expf(sp1[0]) : 0.0f;
    float Mlog = 0.0f;

    // PD-deep register ring prefetch of score rows (clamped, in-bounds).
    float p0[PD], p1[PD];
#pragma unroll
    for (int k = 0; k < PD; ++k) {
        int tt = 1 + k; if (tt > SEQ - 1) tt = SEQ - 1;
        p0[k] = sp0[(size_t)tt * rowstride];
        p1[k] = sp1[(size_t)tt * rowstride];
    }

    for (int t = 1; t < L; ++t) {
        const int pslot = (t - 1) & (PD - 1);
        const float s0 = p0[pslot];
        const float s1 = p1[pslot];
        {   // prefetch t+PD (clamped) into the slot just consumed
            int tn = t + PD; if (tn > SEQ - 1) tn = SEQ - 1;
            p0[pslot] = sp0[(size_t)tn * rowstride];
            p1[pslot] = sp1[(size_t)tn * rowstride];
        }
        const float w0 = __expf(s0);
        const float w1 = __expf(s1);

        // dot_j = sum_i a[i] * eT[i][j], alpha broadcast via shfl.
        // The i=0 broadcast doubles as the delayed-renorm reference r.
        float d00 = 0.f, d01 = 0.f, d02 = 0.f, d03 = 0.f;
        float d10 = 0.f, d11 = 0.f, d12 = 0.f, d13 = 0.f;
        float r;
#pragma unroll
        for (int i = 0; i < 32; i += 4) {
            float e0 = __shfl_sync(FULL, a0, i);
            float e1 = __shfl_sync(FULL, a0, i + 1);
            float e2 = __shfl_sync(FULL, a0, i + 2);
            float e3 = __shfl_sync(FULL, a0, i + 3);
            if (i == 0) r = e0;
            d00 = fmaf(e0, eT0[i],     d00);  d10 = fmaf(e0, eT1[i],     d10);
            d01 = fmaf(e1, eT0[i + 1], d01);  d11 = fmaf(e1, eT1[i + 1], d11);
            d02 = fmaf(e2, eT0[i + 2], d02);  d12 = fmaf(e2, eT1[i + 2], d12);
            d03 = fmaf(e3, eT0[i + 3], d03);  d13 = fmaf(e3, eT1[i + 3], d13);
        }
#pragma unroll
        for (int i = 0; i < 16; i += 4) {
            float e0 = __shfl_sync(FULL, a1, i);
            float e1 = __shfl_sync(FULL, a1, i + 1);
            float e2 = __shfl_sync(FULL, a1, i + 2);
            float e3 = __shfl_sync(FULL, a1, i + 3);
            d00 = fmaf(e0, eT0[32 + i],     d00);  d10 = fmaf(e0, eT1[32 + i],     d10);
            d01 = fmaf(e1, eT0[32 + i + 1], d01);  d11 = fmaf(e1, eT1[32 + i + 1], d11);
            d02 = fmaf(e2, eT0[32 + i + 2], d02);  d12 = fmaf(e2, eT1[32 + i + 2], d12);
            d03 = fmaf(e3, eT0[32 + i + 3], d03);  d13 = fmaf(e3, eT1[32 + i + 3], d13);
        }

        // Delayed renorm: computed concurrently with the dot above.
        const float inv = frcp(r);
        Mlog += __logf(r);
        const float m0 = w0 * inv;
        const float m1 = w1 * inv;

        a0 = ((d00 + d01) + (d02 + d03)) * m0;
        a1 = ((d10 + d11) + (d12 + d13)) * m1;  // 0 for lanes >= 16 (eT1 == 0)
    }

    // logZ = Mlog + log(sum_j a[j])
    float ssum = a0 + a1;
#pragma unroll
    for (int o = 16; o > 0; o >>= 1)
        ssum += __shfl_xor_sync(FULL, ssum, o);

    if (lane == 0) {
        const float logZ = Mlog + __logf(ssum);
        // X warp of the same block finishes in ~13us << our loop: no real wait.
        while (atomicAdd(&sh_flag[wid], 0) == 0) { }
        __threadfence_block();
        const float X = sh_X[wid];
        out[b]         = X;
        out[BATCH + b] = X - logZ;
    }
}

// ---------------------------------------------------------------------------
extern "C" void kernel_launch(void* const* d_in, const int* in_sizes, int n_in,
                              void* d_out, int out_size)
{
    const float* scores  = (const float*)d_in[0];  // (1024, 512, 48) f32
    const int*   target  = (const int*)  d_in[1];  // (1024, 512) i32
    const int*   lengths = (const int*)  d_in[2];  // (512,) i32
    const float* trans   = (const float*)d_in[3];  // (48, 48) f32
    float* out = (float*)d_out;                    // (2, 512) f32

    crf_fused_kernel<<<BATCH / 4, 256>>>(scores, target, lengths, trans, out);
}

// round 5
// speedup vs baseline: 2.5659x; 2.5659x over previous
#include <cuda_runtime.h>

#define SEQ   1024
#define BATCH 512
#define NC    48
#define FULL  0xffffffffu

// ---- packed f32x2 helpers (sm_103a) ------------------------------------
static __device__ __forceinline__ unsigned long long pk2(float lo, float hi) {
    unsigned long long r;
    asm("mov.b64 %0, {%1,%2};" : "=l"(r) : "f"(lo), "f"(hi));
    return r;
}
static __device__ __forceinline__ unsigned long long fma2(
    unsigned long long a, unsigned long long b, unsigned long long c) {
    unsigned long long d;
    asm("fma.rn.f32x2 %0, %1, %2, %3;" : "=l"(d) : "l"(a), "l"(b), "l"(c));
    return d;
}
static __device__ __forceinline__ unsigned long long add2(
    unsigned long long a, unsigned long long b) {
    unsigned long long d;
    asm("add.rn.f32x2 %0, %1, %2;" : "=l"(d) : "l"(a), "l"(b));
    return d;
}
static __device__ __forceinline__ float hadd2(unsigned long long v) {
    float lo, hi;
    asm("mov.b64 {%0,%1}, %2;" : "=f"(lo), "=f"(hi) : "l"(v));
    return lo + hi;
}
static __device__ __forceinline__ float lo2(unsigned long long v) {
    float lo, hi;
    asm("mov.b64 {%0,%1}, %2;" : "=f"(lo), "=f"(hi) : "l"(v));
    return lo;
}
static __device__ __forceinline__ void lds16(
    unsigned long long& x, unsigned long long& y, unsigned int addr) {
    asm volatile("ld.shared.v2.u64 {%0,%1}, [%2];" : "=l"(x), "=l"(y) : "r"(addr));
}
static __device__ __forceinline__ float frcp(float x) {
    float r; asm("rcp.approx.f32 %0, %1;" : "=f"(r) : "f"(x)); return r;
}

// ---------------------------------------------------------------------------
// One warp per batch (block = 128 threads = 4 warps, one warp per SMSP).
// Each warp: (1) computes target-path score X (lane-parallel, ~us), then
// (2) runs the forward recurrence for logZ, then writes both outputs.
//
// logZ: exp-domain u_t = diag(w_t) * E^T * u_{t-1}, E = exp(transitions)
// held in registers as row-paired f32x2. Delayed renormalization by
// alpha_prev[0] (free: low word of the first exchange LDS).
//
// KEY FIX vs R2-R4: the time loop is unrolled x4 so the score-prefetch ring
// uses compile-time indices -> stays in registers. (Runtime ring indices
// demoted the ring to local memory; the STL of each LDG result then blocked
// on DRAM latency EVERY step — the hidden ~430cyc/step in all prior rounds.)
// ---------------------------------------------------------------------------
__global__ __launch_bounds__(128, 1) void crf_fused_kernel(
    const float* __restrict__ scores,
    const int*   __restrict__ target,
    const int*   __restrict__ lengths,
    const float* __restrict__ trans,
    float*       __restrict__ out)
{
    __shared__ float sh_a[4][2][64];   // [warp][pingpong][48 used + pad]

    const int wid  = threadIdx.x >> 5;
    const int lane = threadIdx.x & 31;
    const int b    = blockIdx.x * 4 + wid;

    // ---------------- Phase 1: X (lane-parallel, high MLP) ------------------
    const int L = lengths[b];
    float X = 0.0f;
    for (int t = lane; t < L; t += 32) {
        const int tgt = target[t * BATCH + b];
        float v = scores[((size_t)t * BATCH + b) * NC + tgt];
        if (t > 0) v += trans[target[(t - 1) * BATCH + b] * NC + tgt];
        X += v;
    }
#pragma unroll
    for (int o = 16; o > 0; o >>= 1)
        X += __shfl_xor_sync(FULL, X, o);

    // ---------------- Phase 2: logZ (sequential chain) ----------------------
    const int  c0 = lane;
    const bool v1 = (lane < 16);
    const int  c1 = v1 ? (lane + 32) : lane;   // dup-safe; contributions zeroed

    // exp(transitions) as row-paired f32x2, one column pair per lane.
    unsigned long long eTp0[24], eTp1[24];
#pragma unroll
    for (int k = 0; k < 24; ++k) {
        float x0 = __expf(trans[(2 * k)     * NC + c0]);
        float y0 = __expf(trans[(2 * k + 1) * NC + c0]);
        eTp0[k] = pk2(x0, y0);
        float x1 = v1 ? __expf(trans[(2 * k)     * NC + c1]) : 0.0f;
        float y1 = v1 ? __expf(trans[(2 * k + 1) * NC + c1]) : 0.0f;
        eTp1[k] = pk2(x1, y1);
    }

    const float* sp0 = scores + (size_t)b * NC + c0;
    const float* sp1 = scores + (size_t)b * NC + c1;
    const size_t rs  = (size_t)BATCH * NC;

    float a0   = __expf(sp0[0]);
    float a1   = v1 ? __expf(sp1[0]) : 0.0f;
    float Mlog = 0.0f;

    unsigned int shbase[2];
    shbase[0] = (unsigned int)__cvta_generic_to_shared(&sh_a[wid][0][0]);
    shbase[1] = (unsigned int)__cvta_generic_to_shared(&sh_a[wid][1][0]);

    // 4-deep register ring, COMPILE-TIME indices only (rows 1..4, clamped).
    float p0[4], p1[4];
#pragma unroll
    for (int k = 0; k < 4; ++k) {
        int tt = 1 + k; if (tt > SEQ - 1) tt = SEQ - 1;
        p0[k] = sp0[(size_t)tt * rs];
        p1[k] = sp1[(size_t)tt * rs];
    }

    // One recurrence step. SLOT is a compile-time constant (0..3).
    // Consumes ring slot SLOT, refills it with row min(t+4, SEQ-1).
#define CRF_STEP(T, SLOT)                                                     \
    {                                                                         \
        const float s0 = p0[SLOT];                                            \
        const float s1 = p1[SLOT];                                            \
        int tn = (T) + 4; if (tn > SEQ - 1) tn = SEQ - 1;                     \
        p0[SLOT] = sp0[(size_t)tn * rs];                                      \
        p1[SLOT] = sp1[(size_t)tn * rs];                                      \
        const float w0 = __expf(s0);                                          \
        const float w1 = __expf(s1);                                          \
        {                                                                     \
            float* shp = &sh_a[wid][(SLOT) & 1][0];                           \
            shp[lane]      = a0;                                              \
            shp[32 + lane] = a1;                                              \
        }                                                                     \
        __syncwarp();                                                         \
        const unsigned int sb = shbase[(SLOT) & 1];                           \
        unsigned long long cA0 = 0ull, cA1 = 0ull, cA2 = 0ull, cA3 = 0ull;    \
        unsigned long long cB0 = 0ull, cB1 = 0ull, cB2 = 0ull, cB3 = 0ull;    \
        unsigned long long e01_first = 0ull;                                  \
        _Pragma("unroll")                                                     \
        for (int k = 0; k < 12; k += 2) {                                     \
            unsigned long long x01, x23, y01, y23;                            \
            lds16(x01, x23, sb + 16u * k);                                    \
            lds16(y01, y23, sb + 16u * (k + 1));                              \
            if (k == 0) e01_first = x01;                                      \
            cA0 = fma2(x01, eTp0[2 * k],     cA0);                            \
            cA1 = fma2(x23, eTp0[2 * k + 1], cA1);                            \
            cB0 = fma2(x01, eTp1[2 * k],     cB0);                            \
            cB1 = fma2(x23, eTp1[2 * k + 1], cB1);                            \
            cA2 = fma2(y01, eTp0[2 * k + 2], cA2);                            \
            cA3 = fma2(y23, eTp0[2 * k + 3], cA3);                            \
            cB2 = fma2(y01, eTp1[2 * k + 2], cB2);                            \
            cB3 = fma2(y23, eTp1[2 * k + 3], cB3);                            \
        }                                                                     \
        const float r   = lo2(e01_first);                                     \
        const float inv = frcp(r);                                            \
        Mlog += __logf(r);                                                    \
        const float m0 = w0 * inv;                                            \
        const float m1 = w1 * inv;                                            \
        const float dot0 = hadd2(add2(add2(cA0, cA1), add2(cA2, cA3)));       \
        const float dot1 = hadd2(add2(add2(cB0, cB1), add2(cB2, cB3)));       \
        a0 = dot0 * m0;                                                       \
        a1 = dot1 * m1;                                                       \
    }

    int t = 1;
    for (; t + 3 < L; t += 4) {
        CRF_STEP(t,     0)
        CRF_STEP(t + 1, 1)
        CRF_STEP(t + 2, 2)
        CRF_STEP(t + 3, 3)
    }
    // Tail (<= 3 steps): ring-free, direct loads (latency exposed, ~1us max).
    for (; t < L; ++t) {
        const float s0 = sp0[(size_t)t * rs];
        const float s1 = sp1[(size_t)t * rs];
        const float w0 = __expf(s0);
        const float w1 = __expf(s1);
        {
            float* shp = &sh_a[wid][t & 1][0];
            shp[lane]      = a0;
            shp[32 + lane] = a1;
        }
        __syncwarp();
        const unsigned int sb = shbase[t & 1];
        unsigned long long cA0 = 0ull, cA1 = 0ull, cA2 = 0ull, cA3 = 0ull;
        unsigned long long cB0 = 0ull, cB1 = 0ull, cB2 = 0ull, cB3 = 0ull;
        unsigned long long e01_first = 0ull;
#pragma unroll
        for (int k = 0; k < 12; k += 2) {
            unsigned long long x01, x23, y01, y23;
            lds16(x01, x23, sb + 16u * k);
            lds16(y01, y23, sb + 16u * (k + 1));
            if (k == 0) e01_first = x01;
            cA0 = fma2(x01, eTp0[2 * k],     cA0);
            cA1 = fma2(x23, eTp0[2 * k + 1], cA1);
            cB0 = fma2(x01, eTp1[2 * k],     cB0);
            cB1 = fma2(x23, eTp1[2 * k + 1], cB1);
            cA2 = fma2(y01, eTp0[2 * k + 2], cA2);
            cA3 = fma2(y23, eTp0[2 * k + 3], cA3);
            cB2 = fma2(y01, eTp1[2 * k + 2], cB2);
            cB3 = fma2(y23, eTp1[2 * k + 3], cB3);
        }
        const float r   = lo2(e01_first);
        const float inv = frcp(r);
        Mlog += __logf(r);
        const float m0 = w0 * inv;
        const float m1 = w1 * inv;
        a0 = hadd2(add2(add2(cA0, cA1), add2(cA2, cA3))) * m0;
        a1 = hadd2(add2(add2(cB0, cB1), add2(cB2, cB3))) * m1;
    }
#undef CRF_STEP

    // logZ = Mlog + log(sum_j a[j])
    float ssum = a0 + a1;   // a1 == 0 for lanes >= 16 (eTp1 zeros)
#pragma unroll
    for (int o = 16; o > 0; o >>= 1)
        ssum += __shfl_xor_sync(FULL, ssum, o);

    if (lane == 0) {
        const float logZ = Mlog + __logf(ssum);
        out[b]         = X;
        out[BATCH + b] = X - logZ;
    }
}

// ---------------------------------------------------------------------------
extern "C" void kernel_launch(void* const* d_in, const int* in_sizes, int n_in,
                              void* d_out, int out_size)
{
    const float* scores  = (const float*)d_in[0];  // (1024, 512, 48) f32
    const int*   target  = (const int*)  d_in[1];  // (1024, 512) i32
    const int*   lengths = (const int*)  d_in[2];  // (512,) i32
    const float* trans   = (const float*)d_in[3];  // (48, 48) f32
    float* out = (float*)d_out;                    // (2, 512) f32

    crf_fused_kernel<<<BATCH / 4, 128>>>(scores, target, lengths, trans, out);
}

// round 6
// speedup vs baseline: 3.0222x; 1.1778x over previous
#include <cuda_runtime.h>

#define SEQ   1024
#define BATCH 512
#define NC    48
#define FULL  0xffffffffu

// ---- packed f32x2 helpers (sm_103a) ------------------------------------
static __device__ __forceinline__ unsigned long long pk2(float lo, float hi) {
    unsigned long long r;
    asm("mov.b64 %0, {%1,%2};" : "=l"(r) : "f"(lo), "f"(hi));
    return r;
}
static __device__ __forceinline__ unsigned long long fma2(
    unsigned long long a, unsigned long long b, unsigned long long c) {
    unsigned long long d;
    asm("fma.rn.f32x2 %0, %1, %2, %3;" : "=l"(d) : "l"(a), "l"(b), "l"(c));
    return d;
}
static __device__ __forceinline__ unsigned long long add2(
    unsigned long long a, unsigned long long b) {
    unsigned long long d;
    asm("add.rn.f32x2 %0, %1, %2;" : "=l"(d) : "l"(a), "l"(b));
    return d;
}
static __device__ __forceinline__ float hadd2(unsigned long long v) {
    float lo, hi;
    asm("mov.b64 {%0,%1}, %2;" : "=f"(lo), "=f"(hi) : "l"(v));
    return lo + hi;
}
static __device__ __forceinline__ float lo2(unsigned long long v) {
    float lo, hi;
    asm("mov.b64 {%0,%1}, %2;" : "=f"(lo), "=f"(hi) : "l"(v));
    return lo;
}
static __device__ __forceinline__ void lds16(
    unsigned long long& x, unsigned long long& y, unsigned int addr) {
    asm volatile("ld.shared.v2.u64 {%0,%1}, [%2];" : "=l"(x), "=l"(y) : "r"(addr));
}
static __device__ __forceinline__ float frcp(float x) {
    float r; asm("rcp.approx.f32 %0, %1;" : "=f"(r) : "f"(x)); return r;
}

// The shared inner dot: 12x LDS.128 broadcast + 8 fma2 chains of depth 6.
// Reads 48 floats (the exchanged vector) from sb, tables T0/T1 (24 pairs each).
// Outputs dot0/dot1 and rfirst = exchanged[0] (delayed-renorm reference).
#define CRF_DOT(sb, T0, T1, dot0, dot1, rfirst)                               \
    {                                                                         \
        unsigned long long cA0 = 0ull, cA1 = 0ull, cA2 = 0ull, cA3 = 0ull;    \
        unsigned long long cB0 = 0ull, cB1 = 0ull, cB2 = 0ull, cB3 = 0ull;    \
        unsigned long long e01_first = 0ull;                                  \
        _Pragma("unroll")                                                     \
        for (int k = 0; k < 12; k += 2) {                                     \
            unsigned long long x01, x23, y01, y23;                            \
            lds16(x01, x23, (sb) + 16u * k);                                  \
            lds16(y01, y23, (sb) + 16u * (k + 1));                            \
            if (k == 0) e01_first = x01;                                      \
            cA0 = fma2(x01, T0[2 * k],     cA0);                              \
            cA1 = fma2(x23, T0[2 * k + 1], cA1);                              \
            cB0 = fma2(x01, T1[2 * k],     cB0);                              \
            cB1 = fma2(x23, T1[2 * k + 1], cB1);                              \
            cA2 = fma2(y01, T0[2 * k + 2], cA2);                              \
            cA3 = fma2(y23, T0[2 * k + 3], cA3);                              \
            cB2 = fma2(y01, T1[2 * k + 2], cB2);                              \
            cB3 = fma2(y23, T1[2 * k + 3], cB3);                              \
        }                                                                     \
        rfirst = lo2(e01_first);                                              \
        dot0 = hadd2(add2(add2(cA0, cA1), add2(cA2, cA3)));                   \
        dot1 = hadd2(add2(add2(cB0, cB1), add2(cB2, cB3)));                   \
    }

// ---------------------------------------------------------------------------
// Meet-in-the-middle CRF. Block = 256 threads = 8 warps, 4 batches per block:
//   warp w   (w<4):  FORWARD  chain of batch 4*blk+w  + X score + final write
//   warp w+4:        BACKWARD chain of the same batch
// Forward:  u <- diag(w_t) E^T u,     t = 1 .. h-1        (h = max(1, L/2))
// Backward: x <- E (w_t o x),         t = L-1 .. h, x0 = 1
// logZ = Mf + Mb + log(sum_j u_j * x_j).
// Both chains use exp-domain delayed renormalization by exchanged[0] and
// 4-deep compile-time-indexed register prefetch rings (the R5 fix).
// ---------------------------------------------------------------------------
__global__ __launch_bounds__(256, 1) void crf_mitm_kernel(
    const float* __restrict__ scores,
    const int*   __restrict__ target,
    const int*   __restrict__ lengths,
    const float* __restrict__ trans,
    float*       __restrict__ out)
{
    __shared__ float sh_ex[8][2][64];  // per-warp ping-pong exchange buffers
    __shared__ float sh_v[4][64];      // backward results v
    __shared__ float sh_mb[4];         // backward Mlog

    const int wid  = threadIdx.x >> 5;
    const int lane = threadIdx.x & 31;
    const int b    = blockIdx.x * 4 + (wid & 3);

    const int  L  = lengths[b];
    const int  h  = (L >= 2) ? (L >> 1) : 1;
    const int  c0 = lane;
    const bool v1 = (lane < 16);
    const int  c1 = v1 ? (lane + 32) : lane;   // dup-safe

    const float* sp0 = scores + (size_t)b * NC + c0;
    const float* sp1 = scores + (size_t)b * NC + c1;
    const size_t rs  = (size_t)BATCH * NC;

    unsigned int shbase[2];
    shbase[0] = (unsigned int)__cvta_generic_to_shared(&sh_ex[wid][0][0]);
    shbase[1] = (unsigned int)__cvta_generic_to_shared(&sh_ex[wid][1][0]);

    float a0 = 0.f, a1 = 0.f, Mf = 0.f, X = 0.f;   // forward-role results

    if (wid < 4) {
        // ================= FORWARD role (+ X score) =========================
        // X: lane-parallel gather-sum (high MLP, a few us).
        for (int t = lane; t < L; t += 32) {
            const int tgt = target[t * BATCH + b];
            float v = scores[((size_t)t * BATCH + b) * NC + tgt];
            if (t > 0) v += trans[target[(t - 1) * BATCH + b] * NC + tgt];
            X += v;
        }
#pragma unroll
        for (int o = 16; o > 0; o >>= 1)
            X += __shfl_xor_sync(FULL, X, o);

        // exp(E^T) columns: T0[k] = (E[2k][c],E[2k+1][c]) per owned column c.
        unsigned long long eT0[24], eT1[24];
#pragma unroll
        for (int k = 0; k < 24; ++k) {
            eT0[k] = pk2(__expf(trans[(2 * k)     * NC + c0]),
                         __expf(trans[(2 * k + 1) * NC + c0]));
            eT1[k] = v1 ? pk2(__expf(trans[(2 * k)     * NC + c1]),
                              __expf(trans[(2 * k + 1) * NC + c1]))
                        : 0ull;
        }

        a0 = __expf(sp0[0]);
        a1 = v1 ? __expf(sp1[0]) : 0.0f;

        float p0[4], p1[4];
#pragma unroll
        for (int k = 0; k < 4; ++k) {
            int tt = 1 + k; if (tt > SEQ - 1) tt = SEQ - 1;
            p0[k] = sp0[(size_t)tt * rs];
            p1[k] = sp1[(size_t)tt * rs];
        }

#define FWD_STEP(T, SLOT)                                                     \
    {                                                                         \
        const float s0 = p0[SLOT];                                            \
        const float s1 = p1[SLOT];                                            \
        int tn = (T) + 4; if (tn > SEQ - 1) tn = SEQ - 1;                     \
        p0[SLOT] = sp0[(size_t)tn * rs];                                      \
        p1[SLOT] = sp1[(size_t)tn * rs];                                      \
        const float w0 = __expf(s0);                                          \
        const float w1 = __expf(s1);                                          \
        {                                                                     \
            float* shp = &sh_ex[wid][(SLOT) & 1][0];                          \
            shp[lane]      = a0;                                              \
            shp[32 + lane] = a1;                                              \
        }                                                                     \
        __syncwarp();                                                         \
        float dot0, dot1, r;                                                  \
        CRF_DOT(shbase[(SLOT) & 1], eT0, eT1, dot0, dot1, r)                  \
        const float inv = frcp(r);                                            \
        Mf += __logf(r);                                                      \
        a0 = dot0 * (w0 * inv);                                               \
        a1 = dot1 * (w1 * inv);                                               \
    }

        int t = 1;
        for (; t + 3 < h; t += 4) {
            FWD_STEP(t,     0)
            FWD_STEP(t + 1, 1)
            FWD_STEP(t + 2, 2)
            FWD_STEP(t + 3, 3)
        }
        for (; t < h; ++t) {   // tail <=3: direct loads into slot 0 pattern
            p0[0] = sp0[(size_t)t * rs];
            p1[0] = sp1[(size_t)t * rs];
            const float w0 = __expf(p0[0]);
            const float w1 = __expf(p1[0]);
            {
                float* shp = &sh_ex[wid][t & 1][0];
                shp[lane]      = a0;
                shp[32 + lane] = a1;
            }
            __syncwarp();
            float dot0, dot1, r;
            CRF_DOT(shbase[t & 1], eT0, eT1, dot0, dot1, r)
            const float inv = frcp(r);
            Mf += __logf(r);
            a0 = dot0 * (w0 * inv);
            a1 = dot1 * (w1 * inv);
        }
#undef FWD_STEP
    } else {
        // ================= BACKWARD role ====================================
        // exp(E) rows: T0[k] = (E[c][2k],E[c][2k+1]) per owned row c.
        unsigned long long eE0[24], eE1[24];
#pragma unroll
        for (int k = 0; k < 24; ++k) {
            eE0[k] = pk2(__expf(trans[c0 * NC + 2 * k]),
                         __expf(trans[c0 * NC + 2 * k + 1]));
            eE1[k] = v1 ? pk2(__expf(trans[c1 * NC + 2 * k]),
                              __expf(trans[c1 * NC + 2 * k + 1]))
                        : 0ull;
        }

        float Mb = 0.0f;
        float x0 = 1.0f, x1 = v1 ? 1.0f : 0.0f;   // result if no steps
        const int nsteps = L - h;

        if (nsteps > 0) {
            // g = w_{L-1} o 1  (exchanged vector)
            float g0 = __expf(sp0[(size_t)(L - 1) * rs]);
            float g1 = v1 ? __expf(sp1[(size_t)(L - 1) * rs]) : 0.0f;

            // ring holds rows t-1 (w for the NEXT g), descending.
            float q0[4], q1[4];
#pragma unroll
            for (int k = 0; k < 4; ++k) {
                int tt = L - 2 - k; if (tt < 0) tt = 0;
                q0[k] = sp0[(size_t)tt * rs];
                q1[k] = sp1[(size_t)tt * rs];
            }

#define BWD_STEP(T, SLOT)                                                     \
    {                                                                         \
        const float s0 = q0[SLOT];                                            \
        const float s1 = q1[SLOT];                                            \
        int tn = (T) - 5; if (tn < 0) tn = 0;                                 \
        q0[SLOT] = sp0[(size_t)tn * rs];                                      \
        q1[SLOT] = sp1[(size_t)tn * rs];                                      \
        const float w0 = __expf(s0);                                          \
        const float w1 = __expf(s1);                                          \
        {                                                                     \
            float* shp = &sh_ex[wid][(SLOT) & 1][0];                          \
            shp[lane]      = g0;                                              \
            shp[32 + lane] = g1;                                              \
        }                                                                     \
        __syncwarp();                                                         \
        float dot0, dot1, r;                                                  \
        CRF_DOT(shbase[(SLOT) & 1], eE0, eE1, dot0, dot1, r)                  \
        const float inv = frcp(r);                                            \
        Mb += __logf(r);                                                      \
        x0 = dot0 * inv;                                                      \
        x1 = dot1 * inv;                                                      \
        g0 = x0 * w0;                                                         \
        g1 = x1 * w1;                                                         \
    }

            int t = L - 1;
            for (; t - 3 >= h; t -= 4) {
                BWD_STEP(t,     0)
                BWD_STEP(t - 1, 1)
                BWD_STEP(t - 2, 2)
                BWD_STEP(t - 3, 3)
            }
            for (; t >= h; --t) {  // tail <=3: direct loads
                int tm = t - 1; if (tm < 0) tm = 0;
                const float s0 = sp0[(size_t)tm * rs];
                const float s1 = sp1[(size_t)tm * rs];
                const float w0 = __expf(s0);
                const float w1 = __expf(s1);
                {
                    float* shp = &sh_ex[wid][t & 1][0];
                    shp[lane]      = g0;
                    shp[32 + lane] = g1;
                }
                __syncwarp();
                float dot0, dot1, r;
                CRF_DOT(shbase[t & 1], eE0, eE1, dot0, dot1, r)
                const float inv = frcp(r);
                Mb += __logf(r);
                x0 = dot0 * inv;
                x1 = dot1 * inv;
                g0 = x0 * w0;
                g1 = x1 * w1;
            }
#undef BWD_STEP
        }

        const int w4 = wid - 4;
        sh_v[w4][lane]      = x0;
        sh_v[w4][32 + lane] = x1;   // lanes>=16 write pad (48..63), never read
        if (lane == 0) sh_mb[w4] = Mb;
    }

    __syncthreads();

    if (wid < 4) {
        // Z = Mf + Mb + log(sum_j u_j * v_j)
        const float vv0 = sh_v[wid][lane];
        const float vv1 = v1 ? sh_v[wid][lane + 32] : 0.0f;
        float prod = a0 * vv0 + a1 * vv1;
#pragma unroll
        for (int o = 16; o > 0; o >>= 1)
            prod += __shfl_xor_sync(FULL, prod, o);
        if (lane == 0) {
            const float logZ = Mf + sh_mb[wid] + __logf(prod);
            out[b]         = X;
            out[BATCH + b] = X - logZ;
        }
    }
}

// ---------------------------------------------------------------------------
extern "C" void kernel_launch(void* const* d_in, const int* in_sizes, int n_in,
                              void* d_out, int out_size)
{
    const float* scores  = (const float*)d_in[0];  // (1024, 512, 48) f32
    const int*   target  = (const int*)  d_in[1];  // (1024, 512) i32
    const int*   lengths = (const int*)  d_in[2];  // (512,) i32
    const float* trans   = (const float*)d_in[3];  // (48, 48) f32
    float* out = (float*)d_out;                    // (2, 512) f32

    crf_mitm_kernel<<<BATCH / 4, 256>>>(scores, target, lengths, trans, out);
}

// round 7
// speedup vs baseline: 3.3086x; 1.0948x over previous
#include <cuda_runtime.h>

#define SEQ   1024
#define BATCH 512
#define NC    48
#define FULL  0xffffffffu

// ---- packed f32x2 helpers (sm_103a) ------------------------------------
static __device__ __forceinline__ unsigned long long pk2(float lo, float hi) {
    unsigned long long r;
    asm("mov.b64 %0, {%1,%2};" : "=l"(r) : "f"(lo), "f"(hi));
    return r;
}
static __device__ __forceinline__ unsigned long long fma2(
    unsigned long long a, unsigned long long b, unsigned long long c) {
    unsigned long long d;
    asm("fma.rn.f32x2 %0, %1, %2, %3;" : "=l"(d) : "l"(a), "l"(b), "l"(c));
    return d;
}
static __device__ __forceinline__ unsigned long long add2(
    unsigned long long a, unsigned long long b) {
    unsigned long long d;
    asm("add.rn.f32x2 %0, %1, %2;" : "=l"(d) : "l"(a), "l"(b));
    return d;
}
static __device__ __forceinline__ float hadd2(unsigned long long v) {
    float lo, hi;
    asm("mov.b64 {%0,%1}, %2;" : "=f"(lo), "=f"(hi) : "l"(v));
    return lo + hi;
}
static __device__ __forceinline__ float lo2(unsigned long long v) {
    float lo, hi;
    asm("mov.b64 {%0,%1}, %2;" : "=f"(lo), "=f"(hi) : "l"(v));
    return lo;
}
static __device__ __forceinline__ void lds16(
    unsigned long long& x, unsigned long long& y, unsigned int addr) {
    asm volatile("ld.shared.v2.u64 {%0,%1}, [%2];" : "=l"(x), "=l"(y) : "r"(addr));
}
static __device__ __forceinline__ float frcp(float x) {
    float r; asm("rcp.approx.f32 %0, %1;" : "=f"(r) : "f"(x)); return r;
}

// 36-fma2 dot: every lane computes class A = lane (24 row-pairs) and a
// half-share of class B = 32+(lane>>1) (12 row-pairs, parity-split; the two
// halves are joined by one shfl_xor). B reads its row-pairs via a per-parity
// LDS address (boff = 96*(lane&1)) — no FMA-pipe waste, no SELs.
// rfirst = exchanged[0] (delayed-renorm reference).
#define CRF_DOT36(sb, boff, TA, TB, dotA, dotB, rfirst)                       \
    {                                                                         \
        unsigned long long cA0=0ull,cA1=0ull,cA2=0ull,cA3=0ull;               \
        unsigned long long cB0=0ull,cB1=0ull;                                 \
        unsigned long long e_first=0ull;                                      \
        _Pragma("unroll")                                                     \
        for (int m = 0; m < 6; ++m) {                                         \
            unsigned long long xA0,xA1,xC0,xC1,xB0,xB1;                       \
            lds16(xA0, xA1, (sb) + 16u * m);                                  \
            lds16(xC0, xC1, (sb) + 16u * m + 96u);                            \
            lds16(xB0, xB1, (sb) + 16u * m + (boff));                         \
            if (m == 0) e_first = xA0;                                        \
            cA0 = fma2(xA0, TA[4*m+0], cA0);                                  \
            cA1 = fma2(xA1, TA[4*m+1], cA1);                                  \
            cA2 = fma2(xC0, TA[4*m+2], cA2);                                  \
            cA3 = fma2(xC1, TA[4*m+3], cA3);                                  \
            cB0 = fma2(xB0, TB[2*m+0], cB0);                                  \
            cB1 = fma2(xB1, TB[2*m+1], cB1);                                  \
        }                                                                     \
        rfirst = lo2(e_first);                                                \
        dotA = hadd2(add2(add2(cA0, cA1), add2(cA2, cA3)));                   \
        float _pb = hadd2(add2(cB0, cB1));                                    \
        dotB = _pb + __shfl_xor_sync(FULL, _pb, 1);                           \
    }

// ---------------------------------------------------------------------------
// Meet-in-the-middle CRF. Block = 256 threads, 4 batches per block:
//   warp w (w<4):  FORWARD chain + X over [0,h) + final combine/write
//   warp w+4:      BACKWARD chain + X over [h,L)
// Forward:  u <- diag(w_t) E^T u, t = 1..h-1,   u0 = exp(s_0)
// Backward: v <- E (w_t o v),     t = L-1..h,   v0 = 1
// logZ = Mf + Mb + log(sum_j u_j v_j). Exp-domain, delayed renorm by
// exchanged[0]; 4-deep compile-time-indexed score prefetch rings.
// ---------------------------------------------------------------------------
__global__ __launch_bounds__(256, 1) void crf_mitm_kernel(
    const float* __restrict__ scores,
    const int*   __restrict__ target,
    const int*   __restrict__ lengths,
    const float* __restrict__ trans,
    float*       __restrict__ out)
{
    __shared__ float sh_ex[8][2][64];  // per-warp ping-pong exchange buffers
    __shared__ float sh_v[4][48];      // backward result vectors
    __shared__ float sh_mb[4];         // backward Mlog
    __shared__ float sh_xb[4];         // backward X partial

    const int wid  = threadIdx.x >> 5;
    const int lane = threadIdx.x & 31;
    const int b    = blockIdx.x * 4 + (wid & 3);

    const int L = lengths[b];
    const int h = (L >= 2) ? (L >> 1) : 1;

    const int  cA  = lane;                    // owned class A (0..31)
    const int  cB  = 32 + (lane >> 1);        // shared class B (32..47)
    const int  par = lane & 1;                // parity: which 12-pair half of B
    const unsigned int boff = 96u * (unsigned)par;

    const float* spA = scores + (size_t)b * NC + cA;
    const float* spB = scores + (size_t)b * NC + cB;
    const size_t rs  = (size_t)BATCH * NC;

    unsigned int shbase[2];
    shbase[0] = (unsigned int)__cvta_generic_to_shared(&sh_ex[wid][0][0]);
    shbase[1] = (unsigned int)__cvta_generic_to_shared(&sh_ex[wid][1][0]);

    float aA = 0.f, aB = 0.f, Mf = 0.f, Xpart = 0.f;

    if (wid < 4) {
        // ===================== FORWARD role =================================
        // X over t in [0, h)
        for (int t = lane; t < h; t += 32) {
            const int tgt = target[t * BATCH + b];
            float v = scores[((size_t)t * BATCH + b) * NC + tgt];
            if (t > 0) v += trans[target[(t - 1) * BATCH + b] * NC + tgt];
            Xpart += v;
        }
#pragma unroll
        for (int o = 16; o > 0; o >>= 1)
            Xpart += __shfl_xor_sync(FULL, Xpart, o);

        // Tables: entry(row i, class c) = exp(trans[i][c]).
        // TA layout per m: [4m]=pair 2m, [4m+1]=pair 2m+1,
        //                  [4m+2]=pair 2m+12, [4m+3]=pair 2m+13.
        unsigned long long TA[24], TB[12];
#pragma unroll
        for (int m = 0; m < 6; ++m) {
            int q;
            q = 2*m;      TA[4*m+0] = pk2(__expf(trans[(2*q)*NC + cA]), __expf(trans[(2*q+1)*NC + cA]));
            q = 2*m+1;    TA[4*m+1] = pk2(__expf(trans[(2*q)*NC + cA]), __expf(trans[(2*q+1)*NC + cA]));
            q = 2*m+12;   TA[4*m+2] = pk2(__expf(trans[(2*q)*NC + cA]), __expf(trans[(2*q+1)*NC + cA]));
            q = 2*m+13;   TA[4*m+3] = pk2(__expf(trans[(2*q)*NC + cA]), __expf(trans[(2*q+1)*NC + cA]));
        }
#pragma unroll
        for (int j = 0; j < 12; ++j) {
            const int q = j + 12 * par;
            TB[j] = pk2(__expf(trans[(2*q)*NC + cB]), __expf(trans[(2*q+1)*NC + cB]));
        }

        aA = __expf(spA[0]);
        aB = __expf(spB[0]);

        // 4-deep prefetch ring. Forward refills read rows t+4 <= h+3 <= 515,
        // always in-bounds: NO clamping needed anywhere in the hot loop.
        float pA[4], pB[4];
#pragma unroll
        for (int k = 0; k < 4; ++k) {
            pA[k] = spA[(size_t)(1 + k) * rs];
            pB[k] = spB[(size_t)(1 + k) * rs];
        }

#define FWD_STEP(T, SLOT)                                                     \
    {                                                                         \
        const float sA = pA[SLOT];                                            \
        const float sB = pB[SLOT];                                            \
        pA[SLOT] = spA[(size_t)((T) + 4) * rs];                               \
        pB[SLOT] = spB[(size_t)((T) + 4) * rs];                               \
        const float wA = __expf(sA);                                          \
        const float wB = __expf(sB);                                          \
        {                                                                     \
            float* shp = &sh_ex[wid][(SLOT) & 1][0];                          \
            shp[lane] = aA;                                                   \
            if (!par) shp[cB] = aB;                                           \
        }                                                                     \
        __syncwarp();                                                         \
        float dotA, dotB, r;                                                  \
        CRF_DOT36(shbase[(SLOT) & 1], boff, TA, TB, dotA, dotB, r)            \
        const float inv = frcp(r);                                            \
        Mf += __logf(r);                                                      \
        aA = dotA * (wA * inv);                                               \
        aB = dotB * (wB * inv);                                               \
    }

        int t = 1;
        for (; t + 3 < h; t += 4) {
            FWD_STEP(t,     0)
            FWD_STEP(t + 1, 1)
            FWD_STEP(t + 2, 2)
            FWD_STEP(t + 3, 3)
        }
        // Tail (<=3 steps): direct loads; keep buffer parity = (t-1)&1.
        for (; t < h; ++t) {
            const float sA = spA[(size_t)t * rs];
            const float sB = spB[(size_t)t * rs];
            const float wA = __expf(sA);
            const float wB = __expf(sB);
            {
                float* shp = &sh_ex[wid][(t - 1) & 1][0];
                shp[lane] = aA;
                if (!par) shp[cB] = aB;
            }
            __syncwarp();
            float dotA, dotB, r;
            CRF_DOT36(shbase[(t - 1) & 1], boff, TA, TB, dotA, dotB, r)
            const float inv = frcp(r);
            Mf += __logf(r);
            aA = dotA * (wA * inv);
            aB = dotB * (wB * inv);
        }
#undef FWD_STEP
    } else {
        // ===================== BACKWARD role ================================
        // X over t in [h, L)
        float Xb = 0.0f;
        for (int t = h + lane; t < L; t += 32) {
            const int tgt = target[t * BATCH + b];
            float v = scores[((size_t)t * BATCH + b) * NC + tgt]
                    + trans[target[(t - 1) * BATCH + b] * NC + tgt];
            Xb += v;
        }
#pragma unroll
        for (int o = 16; o > 0; o >>= 1)
            Xb += __shfl_xor_sync(FULL, Xb, o);

        // Tables: entry(col i, class c) = exp(trans[c][i])  (row-major walk).
        unsigned long long TA[24], TB[12];
#pragma unroll
        for (int m = 0; m < 6; ++m) {
            int q;
            q = 2*m;      TA[4*m+0] = pk2(__expf(trans[cA*NC + 2*q]), __expf(trans[cA*NC + 2*q+1]));
            q = 2*m+1;    TA[4*m+1] = pk2(__expf(trans[cA*NC + 2*q]), __expf(trans[cA*NC + 2*q+1]));
            q = 2*m+12;   TA[4*m+2] = pk2(__expf(trans[cA*NC + 2*q]), __expf(trans[cA*NC + 2*q+1]));
            q = 2*m+13;   TA[4*m+3] = pk2(__expf(trans[cA*NC + 2*q]), __expf(trans[cA*NC + 2*q+1]));
        }
#pragma unroll
        for (int j = 0; j < 12; ++j) {
            const int q = j + 12 * par;
            TB[j] = pk2(__expf(trans[cB*NC + 2*q]), __expf(trans[cB*NC + 2*q+1]));
        }

        float Mb = 0.0f;
        float xA = 1.0f, xB = 1.0f;            // v if no steps
        const int nsteps = L - h;

        if (nsteps > 0) {
            float gA = __expf(spA[(size_t)(L - 1) * rs]);
            float gB = __expf(spB[(size_t)(L - 1) * rs]);

            float qA[4], qB[4];
#pragma unroll
            for (int k = 0; k < 4; ++k) {
                int tt = L - 2 - k; if (tt < 0) tt = 0;
                qA[k] = spA[(size_t)tt * rs];
                qB[k] = spB[(size_t)tt * rs];
            }

            // step index = (L-1-t); buffer = step&1. In the macro loop the
            // entry t always has (L-1-t) % 4 == 0, so SLOT&1 is the parity.
#define BWD_STEP(T, SLOT)                                                     \
    {                                                                         \
        const float sA = qA[SLOT];                                            \
        const float sB = qB[SLOT];                                            \
        qA[SLOT] = spA[(size_t)((T) - 5) * rs];                               \
        qB[SLOT] = spB[(size_t)((T) - 5) * rs];                               \
        const float wA = __expf(sA);                                          \
        const float wB = __expf(sB);                                          \
        {                                                                     \
            float* shp = &sh_ex[wid][(SLOT) & 1][0];                          \
            shp[lane] = gA;                                                   \
            if (!par) shp[cB] = gB;                                           \
        }                                                                     \
        __syncwarp();                                                         \
        float dotA, dotB, r;                                                  \
        CRF_DOT36(shbase[(SLOT) & 1], boff, TA, TB, dotA, dotB, r)            \
        const float inv = frcp(r);                                            \
        Mb += __logf(r);                                                      \
        xA = dotA * inv;                                                      \
        xB = dotB * inv;                                                      \
        gA = xA * wA;                                                         \
        gB = xB * wB;                                                         \
    }

            int t = L - 1;
            // unclamped refills need (T-3)-5 >= 0 i.e. t >= 8
            for (; t - 3 >= h && t >= 8; t -= 4) {
                BWD_STEP(t,     0)
                BWD_STEP(t - 1, 1)
                BWD_STEP(t - 2, 2)
                BWD_STEP(t - 3, 3)
            }
            for (; t >= h; --t) {   // tail: direct clamped loads
                int tm = t - 1; if (tm < 0) tm = 0;
                const float sA = spA[(size_t)tm * rs];
                const float sB = spB[(size_t)tm * rs];
                const float wA = __expf(sA);
                const float wB = __expf(sB);
                const int buf = (L - 1 - t) & 1;
                {
                    float* shp = &sh_ex[wid][buf][0];
                    shp[lane] = gA;
                    if (!par) shp[cB] = gB;
                }
                __syncwarp();
                float dotA, dotB, r;
                CRF_DOT36(shbase[buf], boff, TA, TB, dotA, dotB, r)
                const float inv = frcp(r);
                Mb += __logf(r);
                xA = dotA * inv;
                xB = dotB * inv;
                gA = xA * wA;
                gB = xB * wB;
            }
#undef BWD_STEP
        }

        const int w4 = wid - 4;
        sh_v[w4][lane] = xA;
        if (!par) sh_v[w4][cB] = xB;
        if (lane == 0) { sh_mb[w4] = Mb; sh_xb[w4] = Xb; }
    }

    __syncthreads();

    if (wid < 4) {
        // u[32+lane] lives as aB on lane 2*lane (valid for lane < 16)
        const float u32 = __shfl_sync(FULL, aB, (lane << 1) & 31);
        float prod = aA * sh_v[wid][lane];
        if (lane < 16) prod += u32 * sh_v[wid][32 + lane];
#pragma unroll
        for (int o = 16; o > 0; o >>= 1)
            prod += __shfl_xor_sync(FULL, prod, o);
        if (lane == 0) {
            const float X    = Xpart + sh_xb[wid];
            const float logZ = Mf + sh_mb[wid] + __logf(prod);
            out[b]         = X;
            out[BATCH + b] = X - logZ;
        }
    }
}

// ---------------------------------------------------------------------------
extern "C" void kernel_launch(void* const* d_in, const int* in_sizes, int n_in,
                              void* d_out, int out_size)
{
    const float* scores  = (const float*)d_in[0];  // (1024, 512, 48) f32
    const int*   target  = (const int*)  d_in[1];  // (1024, 512) i32
    const int*   lengths = (const int*)  d_in[2];  // (512,) i32
    const float* trans   = (const float*)d_in[3];  // (48, 48) f32
    float* out = (float*)d_out;                    // (2, 512) f32

    crf_mitm_kernel<<<BATCH / 4, 256>>>(scores, target, lengths, trans, out);
}

// round 8
// speedup vs baseline: 3.8262x; 1.1564x over previous
#include <cuda_runtime.h>

#define SEQ   1024
#define BATCH 512
#define NC    48
#define FULL  0xffffffffu

__device__ int g_perm[BATCH];   // rank r -> batch index (descending length)

// ---- packed f32x2 helpers (sm_103a) ------------------------------------
static __device__ __forceinline__ unsigned long long pk2(float lo, float hi) {
    unsigned long long r;
    asm("mov.b64 %0, {%1,%2};" : "=l"(r) : "f"(lo), "f"(hi));
    return r;
}
static __device__ __forceinline__ unsigned long long fma2(
    unsigned long long a, unsigned long long b, unsigned long long c) {
    unsigned long long d;
    asm("fma.rn.f32x2 %0, %1, %2, %3;" : "=l"(d) : "l"(a), "l"(b), "l"(c));
    return d;
}
static __device__ __forceinline__ unsigned long long add2(
    unsigned long long a, unsigned long long b) {
    unsigned long long d;
    asm("add.rn.f32x2 %0, %1, %2;" : "=l"(d) : "l"(a), "l"(b));
    return d;
}
static __device__ __forceinline__ float hadd2(unsigned long long v) {
    float lo, hi;
    asm("mov.b64 {%0,%1}, %2;" : "=f"(lo), "=f"(hi) : "l"(v));
    return lo + hi;
}
static __device__ __forceinline__ float lo2(unsigned long long v) {
    float lo, hi;
    asm("mov.b64 {%0,%1}, %2;" : "=f"(lo), "=f"(hi) : "l"(v));
    return lo;
}
static __device__ __forceinline__ void lds16(
    unsigned long long& x, unsigned long long& y, unsigned int addr) {
    asm volatile("ld.shared.v2.u64 {%0,%1}, [%2];" : "=l"(x), "=l"(y) : "r"(addr));
}
static __device__ __forceinline__ float frcp(float x) {
    float r; asm("rcp.approx.f32 %0, %1;" : "=f"(r) : "f"(x)); return r;
}

// ---------------------------------------------------------------------------
// Rank prologue: counting rank by (length desc, index asc). Deterministic.
// ---------------------------------------------------------------------------
__global__ __launch_bounds__(BATCH) void crf_rank_kernel(
    const int* __restrict__ lengths)
{
    __shared__ int sl[BATCH];
    const int i = threadIdx.x;
    sl[i] = lengths[i];
    __syncthreads();
    const int Li = sl[i];
    int r = 0;
    for (int j = 0; j < BATCH; ++j) {
        const int Lj = sl[j];
        r += (Lj > Li) || (Lj == Li && j < i);
    }
    g_perm[r] = i;
}

// 36-fma2 dot (identical to R7): class A = lane (24 row-pairs) + half-share
// of class B = 32+(lane>>1) (12 row-pairs, parity-split, joined via shfl_xor).
#define CRF_DOT36(sb, boff, TA, TB, dotA, dotB, rfirst)                       \
    {                                                                         \
        unsigned long long cA0=0ull,cA1=0ull,cA2=0ull,cA3=0ull;               \
        unsigned long long cB0=0ull,cB1=0ull;                                 \
        unsigned long long e_first=0ull;                                      \
        _Pragma("unroll")                                                     \
        for (int m = 0; m < 6; ++m) {                                         \
            unsigned long long xA0,xA1,xC0,xC1,xB0,xB1;                       \
            lds16(xA0, xA1, (sb) + 16u * m);                                  \
            lds16(xC0, xC1, (sb) + 16u * m + 96u);                            \
            lds16(xB0, xB1, (sb) + 16u * m + (boff));                         \
            if (m == 0) e_first = xA0;                                        \
            cA0 = fma2(xA0, TA[4*m+0], cA0);                                  \
            cA1 = fma2(xA1, TA[4*m+1], cA1);                                  \
            cA2 = fma2(xC0, TA[4*m+2], cA2);                                  \
            cA3 = fma2(xC1, TA[4*m+3], cA3);                                  \
            cB0 = fma2(xB0, TB[2*m+0], cB0);                                  \
            cB1 = fma2(xB1, TB[2*m+1], cB1);                                  \
        }                                                                     \
        rfirst = lo2(e_first);                                                \
        dotA = hadd2(add2(add2(cA0, cA1), add2(cA2, cA3)));                   \
        float _pb = hadd2(add2(cB0, cB1));                                    \
        dotB = _pb + __shfl_xor_sync(FULL, _pb, 1);                           \
    }

// ---------------------------------------------------------------------------
// Meet-in-the-middle CRF with length-aware scheduling.
// Block k owns length-ranks {k, k+128, k+256, k+384} (slots 0..3).
// Warp->(slot, role) chosen so each SMSP pairs a LONG half-chain with a
// SHORT one:  w0:(0,F) w1:(0,B) w2:(1,F) w3:(1,B)
//             w4:(3,B) w5:(3,F) w6:(2,B) w7:(2,F)
// (SMSP = wid&3: SMSP0 = fwd(rank k) + bwd(rank k+384), etc.)
// ---------------------------------------------------------------------------
__global__ __launch_bounds__(256, 1) void crf_mitm_kernel(
    const float* __restrict__ scores,
    const int*   __restrict__ target,
    const int*   __restrict__ lengths,
    const float* __restrict__ trans,
    float*       __restrict__ out)
{
    __shared__ float sh_ex[8][2][64];  // per-warp ping-pong exchange buffers
    __shared__ float sh_v[4][48];      // backward result vectors (per slot)
    __shared__ float sh_mb[4];         // backward Mlog
    __shared__ float sh_xb[4];         // backward X partial

    const int wid  = threadIdx.x >> 5;
    const int lane = threadIdx.x & 31;

    const int  slot  = (wid < 4) ? (wid >> 1) : (3 - ((wid - 4) >> 1));
    const bool isfwd = !((wid & 1) ^ ((wid >> 2) & 1));
    const int  b     = g_perm[blockIdx.x + 128 * slot];

    const int L = lengths[b];
    const int h = (L >= 2) ? (L >> 1) : 1;

    const int  cA  = lane;
    const int  cB  = 32 + (lane >> 1);
    const int  par = lane & 1;
    const unsigned int boff = 96u * (unsigned)par;

    const float* spA = scores + (size_t)b * NC + cA;
    const float* spB = scores + (size_t)b * NC + cB;
    const size_t rs  = (size_t)BATCH * NC;

    unsigned int shbase[2];
    shbase[0] = (unsigned int)__cvta_generic_to_shared(&sh_ex[wid][0][0]);
    shbase[1] = (unsigned int)__cvta_generic_to_shared(&sh_ex[wid][1][0]);

    float aA = 0.f, aB = 0.f, Mf = 0.f, Xpart = 0.f;

    if (isfwd) {
        // ===================== FORWARD role =================================
        for (int t = lane; t < h; t += 32) {
            const int tgt = target[t * BATCH + b];
            float v = scores[((size_t)t * BATCH + b) * NC + tgt];
            if (t > 0) v += trans[target[(t - 1) * BATCH + b] * NC + tgt];
            Xpart += v;
        }
#pragma unroll
        for (int o = 16; o > 0; o >>= 1)
            Xpart += __shfl_xor_sync(FULL, Xpart, o);

        unsigned long long TA[24], TB[12];
#pragma unroll
        for (int m = 0; m < 6; ++m) {
            int q;
            q = 2*m;      TA[4*m+0] = pk2(__expf(trans[(2*q)*NC + cA]), __expf(trans[(2*q+1)*NC + cA]));
            q = 2*m+1;    TA[4*m+1] = pk2(__expf(trans[(2*q)*NC + cA]), __expf(trans[(2*q+1)*NC + cA]));
            q = 2*m+12;   TA[4*m+2] = pk2(__expf(trans[(2*q)*NC + cA]), __expf(trans[(2*q+1)*NC + cA]));
            q = 2*m+13;   TA[4*m+3] = pk2(__expf(trans[(2*q)*NC + cA]), __expf(trans[(2*q+1)*NC + cA]));
        }
#pragma unroll
        for (int j = 0; j < 12; ++j) {
            const int q = j + 12 * par;
            TB[j] = pk2(__expf(trans[(2*q)*NC + cB]), __expf(trans[(2*q+1)*NC + cB]));
        }

        aA = __expf(spA[0]);
        aB = __expf(spB[0]);

        float pA[4], pB[4];
#pragma unroll
        for (int k = 0; k < 4; ++k) {
            pA[k] = spA[(size_t)(1 + k) * rs];
            pB[k] = spB[(size_t)(1 + k) * rs];
        }

#define FWD_STEP(T, SLOT)                                                     \
    {                                                                         \
        const float sA = pA[SLOT];                                            \
        const float sB = pB[SLOT];                                            \
        pA[SLOT] = spA[(size_t)((T) + 4) * rs];                               \
        pB[SLOT] = spB[(size_t)((T) + 4) * rs];                               \
        const float wA = __expf(sA);                                          \
        const float wB = __expf(sB);                                          \
        {                                                                     \
            float* shp = &sh_ex[wid][(SLOT) & 1][0];                          \
            shp[lane] = aA;                                                   \
            if (!par) shp[cB] = aB;                                           \
        }                                                                     \
        __syncwarp();                                                         \
        float dotA, dotB, r;                                                  \
        CRF_DOT36(shbase[(SLOT) & 1], boff, TA, TB, dotA, dotB, r)            \
        const float inv = frcp(r);                                            \
        Mf += __logf(r);                                                      \
        aA = dotA * (wA * inv);                                               \
        aB = dotB * (wB * inv);                                               \
    }

        int t = 1;
        for (; t + 3 < h; t += 4) {
            FWD_STEP(t,     0)
            FWD_STEP(t + 1, 1)
            FWD_STEP(t + 2, 2)
            FWD_STEP(t + 3, 3)
        }
        for (; t < h; ++t) {
            const float sA = spA[(size_t)t * rs];
            const float sB = spB[(size_t)t * rs];
            const float wA = __expf(sA);
            const float wB = __expf(sB);
            {
                float* shp = &sh_ex[wid][(t - 1) & 1][0];
                shp[lane] = aA;
                if (!par) shp[cB] = aB;
            }
            __syncwarp();
            float dotA, dotB, r;
            CRF_DOT36(shbase[(t - 1) & 1], boff, TA, TB, dotA, dotB, r)
            const float inv = frcp(r);
            Mf += __logf(r);
            aA = dotA * (wA * inv);
            aB = dotB * (wB * inv);
        }
#undef FWD_STEP
    } else {
        // ===================== BACKWARD role ================================
        float Xb = 0.0f;
        for (int t = h + lane; t < L; t += 32) {
            const int tgt = target[t * BATCH + b];
            float v = scores[((size_t)t * BATCH + b) * NC + tgt]
                    + trans[target[(t - 1) * BATCH + b] * NC + tgt];
            Xb += v;
        }
#pragma unroll
        for (int o = 16; o > 0; o >>= 1)
            Xb += __shfl_xor_sync(FULL, Xb, o);

        unsigned long long TA[24], TB[12];
#pragma unroll
        for (int m = 0; m < 6; ++m) {
            int q;
            q = 2*m;      TA[4*m+0] = pk2(__expf(trans[cA*NC + 2*q]), __expf(trans[cA*NC + 2*q+1]));
            q = 2*m+1;    TA[4*m+1] = pk2(__expf(trans[cA*NC + 2*q]), __expf(trans[cA*NC + 2*q+1]));
            q = 2*m+12;   TA[4*m+2] = pk2(__expf(trans[cA*NC + 2*q]), __expf(trans[cA*NC + 2*q+1]));
            q = 2*m+13;   TA[4*m+3] = pk2(__expf(trans[cA*NC + 2*q]), __expf(trans[cA*NC + 2*q+1]));
        }
#pragma unroll
        for (int j = 0; j < 12; ++j) {
            const int q = j + 12 * par;
            TB[j] = pk2(__expf(trans[cB*NC + 2*q]), __expf(trans[cB*NC + 2*q+1]));
        }

        float Mb = 0.0f;
        float xA = 1.0f, xB = 1.0f;
        const int nsteps = L - h;

        if (nsteps > 0) {
            float gA = __expf(spA[(size_t)(L - 1) * rs]);
            float gB = __expf(spB[(size_t)(L - 1) * rs]);

            float qA[4], qB[4];
#pragma unroll
            for (int k = 0; k < 4; ++k) {
                int tt = L - 2 - k; if (tt < 0) tt = 0;
                qA[k] = spA[(size_t)tt * rs];
                qB[k] = spB[(size_t)tt * rs];
            }

#define BWD_STEP(T, SLOT)                                                     \
    {                                                                         \
        const float sA = qA[SLOT];                                            \
        const float sB = qB[SLOT];                                            \
        qA[SLOT] = spA[(size_t)((T) - 5) * rs];                               \
        qB[SLOT] = spB[(size_t)((T) - 5) * rs];                               \
        const float wA = __expf(sA);                                          \
        const float wB = __expf(sB);                                          \
        {                                                                     \
            float* shp = &sh_ex[wid][(SLOT) & 1][0];                          \
            shp[lane] = gA;                                                   \
            if (!par) shp[cB] = gB;                                           \
        }                                                                     \
        __syncwarp();                                                         \
        float dotA, dotB, r;                                                  \
        CRF_DOT36(shbase[(SLOT) & 1], boff, TA, TB, dotA, dotB, r)            \
        const float inv = frcp(r);                                            \
        Mb += __logf(r);                                                      \
        xA = dotA * inv;                                                      \
        xB = dotB * inv;                                                      \
        gA = xA * wA;                                                         \
        gB = xB * wB;                                                         \
    }

            int t = L - 1;
            for (; t - 3 >= h && t >= 8; t -= 4) {
                BWD_STEP(t,     0)
                BWD_STEP(t - 1, 1)
                BWD_STEP(t - 2, 2)
                BWD_STEP(t - 3, 3)
            }
            for (; t >= h; --t) {
                int tm = t - 1; if (tm < 0) tm = 0;
                const float sA = spA[(size_t)tm * rs];
                const float sB = spB[(size_t)tm * rs];
                const float wA = __expf(sA);
                const float wB = __expf(sB);
                const int buf = (L - 1 - t) & 1;
                {
                    float* shp = &sh_ex[wid][buf][0];
                    shp[lane] = gA;
                    if (!par) shp[cB] = gB;
                }
                __syncwarp();
                float dotA, dotB, r;
                CRF_DOT36(shbase[buf], boff, TA, TB, dotA, dotB, r)
                const float inv = frcp(r);
                Mb += __logf(r);
                xA = dotA * inv;
                xB = dotB * inv;
                gA = xA * wA;
                gB = xB * wB;
            }
#undef BWD_STEP
        }

        sh_v[slot][lane] = xA;
        if (!par) sh_v[slot][cB] = xB;
        if (lane == 0) { sh_mb[slot] = Mb; sh_xb[slot] = Xb; }
    }

    __syncthreads();

    if (isfwd) {
        // u[32+lane] lives as aB on lane 2*lane (valid for lane < 16)
        const float u32 = __shfl_sync(FULL, aB, (lane << 1) & 31);
        float prod = aA * sh_v[slot][lane];
        if (lane < 16) prod += u32 * sh_v[slot][32 + lane];
#pragma unroll
        for (int o = 16; o > 0; o >>= 1)
            prod += __shfl_xor_sync(FULL, prod, o);
        if (lane == 0) {
            const float X    = Xpart + sh_xb[slot];
            const float logZ = Mf + sh_mb[slot] + __logf(prod);
            out[b]         = X;
            out[BATCH + b] = X - logZ;
        }
    }
}

// ---------------------------------------------------------------------------
extern "C" void kernel_launch(void* const* d_in, const int* in_sizes, int n_in,
                              void* d_out, int out_size)
{
    const float* scores  = (const float*)d_in[0];  // (1024, 512, 48) f32
    const int*   target  = (const int*)  d_in[1];  // (1024, 512) i32
    const int*   lengths = (const int*)  d_in[2];  // (512,) i32
    const float* trans   = (const float*)d_in[3];  // (48, 48) f32
    float* out = (float*)d_out;                    // (2, 512) f32

    crf_rank_kernel<<<1, BATCH>>>(lengths);
    crf_mitm_kernel<<<BATCH / 4, 256>>>(scores, target, lengths, trans, out);
}